// round 15
// baseline (speedup 1.0000x reference)
#include <cuda_runtime.h>
#include <cuda_bf16.h>
#include <cstdint>

#define T_DIM 2048
#define S_DIM 2048
#define B_DIM 4
#define H_DIM 8
#define NOUT 512
#define HIDW 256
#define NROWS (T_DIM*B_DIM)

// scratch (device globals; no allocation allowed)
__device__ __align__(128) __nv_bfloat16 g_qkv[3][(size_t)NROWS*NOUT];
__device__ __align__(128) float g_ctx[(size_t)NROWS*NOUT];
__device__ __align__(128) __nv_bfloat16 g_hid[3][(size_t)NROWS*HIDW];
__device__ __align__(128) __nv_bfloat16 g_w1h[3][64*HIDW];
__device__ __align__(128) __nv_bfloat16 g_w1l[64*HIDW];
__device__ __align__(128) __nv_bfloat16 g_w2h[3][HIDW*NOUT];
__device__ __align__(128) __nv_bfloat16 g_w2l[HIDW*NOUT];

// ---------------------------------------------------------------------------
// helpers
// ---------------------------------------------------------------------------
__device__ __forceinline__ uint32_t smem_u32(const void* p) {
    return (uint32_t)__cvta_generic_to_shared(p);
}
__device__ __forceinline__ uint32_t pkbf(float a, float b) {
    __nv_bfloat162 t = __floats2bfloat162_rn(a, b);
    return *reinterpret_cast<uint32_t*>(&t);
}
__device__ __forceinline__ void ldmx4(uint32_t& r0, uint32_t& r1, uint32_t& r2, uint32_t& r3, uint32_t a) {
    asm volatile("ldmatrix.sync.aligned.m8n8.x4.shared.b16 {%0,%1,%2,%3}, [%4];"
                 : "=r"(r0), "=r"(r1), "=r"(r2), "=r"(r3) : "r"(a));
}
__device__ __forceinline__ void ldmx4t(uint32_t& r0, uint32_t& r1, uint32_t& r2, uint32_t& r3, uint32_t a) {
    asm volatile("ldmatrix.sync.aligned.m8n8.x4.trans.shared.b16 {%0,%1,%2,%3}, [%4];"
                 : "=r"(r0), "=r"(r1), "=r"(r2), "=r"(r3) : "r"(a));
}
__device__ __forceinline__ void ldmx2t(uint32_t& r0, uint32_t& r1, uint32_t a) {
    asm volatile("ldmatrix.sync.aligned.m8n8.x2.trans.shared.b16 {%0,%1}, [%2];"
                 : "=r"(r0), "=r"(r1) : "r"(a));
}
__device__ __forceinline__ void mma_bf16(float& c0, float& c1, float& c2, float& c3,
                                         const uint32_t a[4], uint32_t b0, uint32_t b1) {
    asm volatile("mma.sync.aligned.m16n8k16.row.col.f32.bf16.bf16.f32 "
                 "{%0,%1,%2,%3}, {%4,%5,%6,%7}, {%8,%9}, {%0,%1,%2,%3};"
                 : "+f"(c0), "+f"(c1), "+f"(c2), "+f"(c3)
                 : "r"(a[0]), "r"(a[1]), "r"(a[2]), "r"(a[3]), "r"(b0), "r"(b1));
}
__device__ __forceinline__ void cp16(uint32_t dst, const void* src) {
    asm volatile("cp.async.cg.shared.global [%0], [%1], 16;" :: "r"(dst), "l"(src));
}
__device__ __forceinline__ void cp_commit() { asm volatile("cp.async.commit_group;"); }
__device__ __forceinline__ void cp_wait1()  { asm volatile("cp.async.wait_group 1;"); }
__device__ __forceinline__ void cp_wait0()  { asm volatile("cp.async.wait_group 0;"); }

// ---------------------------------------------------------------------------
// Kernel 0: weight conversion fp32 -> bf16 hi (+lo residual for V path)
// ---------------------------------------------------------------------------
struct PrepSrc { const float* w[6]; };

__global__ void prep_kernel(PrepSrc S)
{
    int e = blockIdx.y;
    const float* src = S.w[e];
    __nv_bfloat16* hi; __nv_bfloat16* lo = nullptr; int n;
    switch (e) {
        case 0: hi = g_w1h[0]; n = 64*HIDW; break;
        case 1: hi = g_w1h[1]; n = 64*HIDW; break;
        case 2: hi = g_w1h[2]; lo = g_w1l; n = 64*HIDW; break;
        case 3: hi = g_w2h[0]; n = HIDW*NOUT; break;
        case 4: hi = g_w2h[1]; n = HIDW*NOUT; break;
        default: hi = g_w2h[2]; lo = g_w2l; n = HIDW*NOUT; break;
    }
    int i = blockIdx.x * blockDim.x + threadIdx.x;
    if (i < n) {
        float w = src[i];
        __nv_bfloat16 h = __float2bfloat16(w);
        hi[i] = h;
        if (lo) lo[i] = __float2bfloat16(w - __bfloat162float(h));
    }
}

// ---------------------------------------------------------------------------
// Kernel 1 (P1): H = relu(X @ W1 + b1), bf16 out. CTA = 128 rows, 8 warps.
// V (p==2) runs split hi+lo passes over W1.  (unchanged)
// ---------------------------------------------------------------------------
struct P1Args { const float* x[3]; const float* b1[3]; };

#define P1_SMEM (128*72*2 + 2*64*264*2)

__global__ void __launch_bounds__(256) p1_kernel(P1Args A)
{
    extern __shared__ char sm[];
    __nv_bfloat16* Xs  = reinterpret_cast<__nv_bfloat16*>(sm);            // [128][72]
    __nv_bfloat16* W1s = reinterpret_cast<__nv_bfloat16*>(sm + 128*72*2); // [2][64][264]

    int p = blockIdx.y;
    const float* x   = A.x[p];
    const float* b1p = A.b1[p];
    int tid = threadIdx.x, w = tid >> 5, lane = tid & 31;
    int r0 = blockIdx.x * 128;

    {
        int r = tid >> 1, c0 = (tid & 1) * 32;
        const float4* src = reinterpret_cast<const float4*>(&x[(size_t)(r0 + r)*64 + c0]);
        __nv_bfloat162 tmp[16];
        #pragma unroll
        for (int i = 0; i < 8; i++) {
            float4 v = src[i];
            tmp[2*i]   = __floats2bfloat162_rn(v.x, v.y);
            tmp[2*i+1] = __floats2bfloat162_rn(v.z, v.w);
        }
        uint4* dst = reinterpret_cast<uint4*>(&Xs[r*72 + c0]);
        const uint4* ts = reinterpret_cast<const uint4*>(tmp);
        dst[0] = ts[0]; dst[1] = ts[1]; dst[2] = ts[2]; dst[3] = ts[3];
    }
    {
        int nsrc = (p == 2) ? 2 : 1;
        for (int s = 0; s < nsrc; s++) {
            const __nv_bfloat16* g = (s == 0) ? g_w1h[p] : g_w1l;
            #pragma unroll
            for (int j = 0; j < 8; j++) {
                int i = tid + j*256;
                int row = i >> 5, c8 = i & 31;
                *reinterpret_cast<uint4*>(&W1s[s*64*264 + row*264 + c8*8]) =
                    *reinterpret_cast<const uint4*>(&g[row*HIDW + c8*8]);
            }
        }
    }
    __syncthreads();

    int l7 = lane & 7, lg = (lane >> 3) & 1, lh = lane >> 4;
    uint32_t af[4][4];
    #pragma unroll
    for (int kc = 0; kc < 4; kc++)
        ldmx4(af[kc][0], af[kc][1], af[kc][2], af[kc][3],
              smem_u32(&Xs[(w*16 + l7 + lg*8)*72 + kc*16 + lh*8]));

    int nsrc = (p == 2) ? 2 : 1;
    int r = lane >> 2, c = (lane & 3)*2;

    #pragma unroll 1
    for (int half = 0; half < 2; half++) {
        float acc[16][4];
        #pragma unroll
        for (int nf = 0; nf < 16; nf++)
            #pragma unroll
            for (int i = 0; i < 4; i++) acc[nf][i] = 0.f;

        #pragma unroll 1
        for (int s = 0; s < nsrc; s++) {
            const __nv_bfloat16* Wb = W1s + s*64*264;
            #pragma unroll
            for (int nf = 0; nf < 16; nf++) {
                #pragma unroll
                for (int kc = 0; kc < 4; kc++) {
                    uint32_t b0, b1;
                    ldmx2t(b0, b1, smem_u32(&Wb[(kc*16 + lg*8 + l7)*264 + half*128 + nf*8]));
                    mma_bf16(acc[nf][0], acc[nf][1], acc[nf][2], acc[nf][3], af[kc], b0, b1);
                }
            }
        }
        #pragma unroll
        for (int nf = 0; nf < 16; nf++) {
            int col = half*128 + nf*8 + c;
            float2 bb = *reinterpret_cast<const float2*>(&b1p[col]);
            float v0 = fmaxf(acc[nf][0] + bb.x, 0.f);
            float v1 = fmaxf(acc[nf][1] + bb.y, 0.f);
            float v2 = fmaxf(acc[nf][2] + bb.x, 0.f);
            float v3 = fmaxf(acc[nf][3] + bb.y, 0.f);
            size_t base = (size_t)(r0 + w*16 + r)*HIDW + col;
            *reinterpret_cast<uint32_t*>(&g_hid[p][base])            = pkbf(v0, v1);
            *reinterpret_cast<uint32_t*>(&g_hid[p][base + 8*HIDW])   = pkbf(v2, v3);
        }
    }
}

// ---------------------------------------------------------------------------
// Kernel 2 (P2): Y = H @ W2 + b2 (scale), bf16 out to g_qkv. (unchanged)
// ---------------------------------------------------------------------------
struct P2Args { const float* b2[3]; float scale[3]; };

#define P2_AS 264
#define P2_SMEM (128*P2_AS*2 + 2*32*P2_AS*2)

__global__ void __launch_bounds__(512) p2_kernel(P2Args A2)
{
    extern __shared__ char sm[];
    __nv_bfloat16* As = reinterpret_cast<__nv_bfloat16*>(sm);               // [128][264]
    __nv_bfloat16* Bs = reinterpret_cast<__nv_bfloat16*>(sm + 128*P2_AS*2); // [2][32][264]

    int p = blockIdx.z, nh = blockIdx.y;
    int r0 = blockIdx.x * 128;
    int tid = threadIdx.x, w = tid >> 5, lane = tid & 31;
    int wm = w & 3, wn = w >> 2;
    int l7 = lane & 7, lg = (lane >> 3) & 1, lh = lane >> 4;

    {
        #pragma unroll
        for (int j = 0; j < 8; j++) {
            int i = tid + j*512;
            int row = i >> 5, c8 = i & 31;
            cp16(smem_u32(&As[row*P2_AS + c8*8]),
                 &g_hid[p][(size_t)(r0 + row)*HIDW + c8*8]);
        }
        cp_commit();
    }

    auto issue_b = [&](int kk) {
        const __nv_bfloat16* w2p = (kk < 8) ? g_w2h[p] : g_w2l;
        int k0 = (kk & 7) * 32;
        int buf = kk & 1;
        #pragma unroll
        for (int j = 0; j < 2; j++) {
            int i = tid + j*512;
            int row = i >> 5, c8 = i & 31;
            cp16(smem_u32(&Bs[buf*32*P2_AS + row*P2_AS + c8*8]),
                 &w2p[(size_t)(k0 + row)*NOUT + nh*256 + c8*8]);
        }
        cp_commit();
    };

    issue_b(0);

    float acc[2][8][4];
    #pragma unroll
    for (int m = 0; m < 2; m++)
        #pragma unroll
        for (int nf = 0; nf < 8; nf++)
            #pragma unroll
            for (int i = 0; i < 4; i++) acc[m][nf][i] = 0.f;

    int NC = (p == 2) ? 16 : 8;
    #pragma unroll 1
    for (int kk = 0; kk < NC; kk++) {
        if (kk + 1 < NC) { issue_b(kk + 1); cp_wait1(); }
        else             { cp_wait0(); }
        __syncthreads();

        int buf = kk & 1;
        uint32_t af[2][2][4];
        #pragma unroll
        for (int m = 0; m < 2; m++)
            #pragma unroll
            for (int kc = 0; kc < 2; kc++)
                ldmx4(af[m][kc][0], af[m][kc][1], af[m][kc][2], af[m][kc][3],
                      smem_u32(&As[(wm*32 + m*16 + l7 + lg*8)*P2_AS + (kk & 7)*32 + kc*16 + lh*8]));

        #pragma unroll
        for (int nf = 0; nf < 8; nf++) {
            #pragma unroll
            for (int kc = 0; kc < 2; kc++) {
                uint32_t b0, b1;
                ldmx2t(b0, b1, smem_u32(&Bs[buf*32*P2_AS + (kc*16 + lg*8 + l7)*P2_AS + wn*64 + nf*8]));
                mma_bf16(acc[0][nf][0], acc[0][nf][1], acc[0][nf][2], acc[0][nf][3], af[0][kc], b0, b1);
                mma_bf16(acc[1][nf][0], acc[1][nf][1], acc[1][nf][2], acc[1][nf][3], af[1][kc], b0, b1);
            }
        }
        __syncthreads();
    }

    const float* b2p = A2.b2[p];
    float scale = A2.scale[p];
    int r = lane >> 2, c = (lane & 3)*2;
    #pragma unroll
    for (int m = 0; m < 2; m++) {
        #pragma unroll
        for (int nf = 0; nf < 8; nf++) {
            int row = r0 + wm*32 + m*16 + r;
            int col = nh*256 + wn*64 + nf*8 + c;
            float2 bb = *reinterpret_cast<const float2*>(&b2p[col]);
            float v0 = (acc[m][nf][0] + bb.x) * scale;
            float v1 = (acc[m][nf][1] + bb.y) * scale;
            float v2 = (acc[m][nf][2] + bb.x) * scale;
            float v3 = (acc[m][nf][3] + bb.y) * scale;
            *reinterpret_cast<uint32_t*>(&g_qkv[p][(size_t)row*NOUT + col])       = pkbf(v0, v1);
            *reinterpret_cast<uint32_t*>(&g_qkv[p][(size_t)(row + 8)*NOUT + col]) = pkbf(v2, v3);
        }
    }
}

// ---------------------------------------------------------------------------
// Kernel 3: flash attention. CTA = (b,h,128 t-rows), 4 warps x 32 rows.
// R11: mask float2s prefetched into registers at tile top (issued before the
// cp.async wait, consumed after QK mma) — removes the long-scoreboard stall
// in the exp section. qf fragments reloaded per tile from smem-resident Qs
// to offset the prefetch register cost. Numerics identical to R10.
// ---------------------------------------------------------------------------
#define ATT_SMEM (128*72*2 + 4*64*72*2)

__global__ void __launch_bounds__(128, 2) attn_kernel(const float* __restrict__ mask)
{
    extern __shared__ char smc[];
    __nv_bfloat16* Qs = reinterpret_cast<__nv_bfloat16*>(smc);                      // [128][72]
    __nv_bfloat16* Ks = reinterpret_cast<__nv_bfloat16*>(smc + 128*72*2);           // [2][64][72]
    __nv_bfloat16* Vs = reinterpret_cast<__nv_bfloat16*>(smc + 128*72*2 + 2*64*72*2);

    int tid = threadIdx.x, w = tid >> 5, lane = tid & 31;
    int t0 = blockIdx.x * 128, h = blockIdx.y, b = blockIdx.z;
    const __nv_bfloat16* qg = g_qkv[0];
    const __nv_bfloat16* kg = g_qkv[1];
    const __nv_bfloat16* vg = g_qkv[2];

    // load Q tile [128][64] (one row per thread)
    {
        const uint4* src = reinterpret_cast<const uint4*>(
            &qg[((size_t)(t0 + tid)*B_DIM + b)*NOUT + h*64]);
        uint4* dst = reinterpret_cast<uint4*>(&Qs[tid*72]);
        #pragma unroll
        for (int i = 0; i < 8; i++) dst[i] = src[i];
    }

    // K/V staging: 128 threads, 2 per row, 32 cols (64B = 4x cp16) each
    int lr = tid >> 1, lpart = tid & 1;
    const __nv_bfloat16* kbase = &kg[((size_t)lr*B_DIM + b)*NOUT + h*64 + lpart*32];
    const __nv_bfloat16* vbase = &vg[((size_t)lr*B_DIM + b)*NOUT + h*64 + lpart*32];
    uint32_t dK0 = smem_u32(&Ks[lr*72 + lpart*32]);
    uint32_t dV0 = smem_u32(&Vs[lr*72 + lpart*32]);
    const uint32_t bufstride = 64*72*2;

    auto issue = [&](int it, int buf) {
        size_t off = (size_t)it * 64 * B_DIM * NOUT;
        const char* sK = reinterpret_cast<const char*>(kbase + off);
        const char* sV = reinterpret_cast<const char*>(vbase + off);
        uint32_t dK = dK0 + buf*bufstride, dV = dV0 + buf*bufstride;
        #pragma unroll
        for (int i = 0; i < 4; i++) {
            cp16(dK + i*16, sK + i*16);
            cp16(dV + i*16, sV + i*16);
        }
        cp_commit();
    };

    issue(0, 0);
    __syncthreads();   // Qs ready

    int l7 = lane & 7;
    int lb3 = (lane >> 3) & 1, lb4 = (lane >> 4) & 1;
    int g2 = lane >> 3;

    float accO[2][8][4];
    #pragma unroll
    for (int band = 0; band < 2; band++)
        #pragma unroll
        for (int d = 0; d < 8; d++)
            #pragma unroll
            for (int i = 0; i < 4; i++) accO[band][d][i] = 0.f;

    float ls[2][2] = {{0.f, 0.f}, {0.f, 0.f}};
    const float* mrow[2];
    #pragma unroll
    for (int band = 0; band < 2; band++)
        mrow[band] = mask + ((size_t)b*T_DIM + (t0 + w*32 + band*16 + (lane >> 2)))*S_DIM + (lane & 3)*2;

    #pragma unroll 1
    for (int it = 0; it < S_DIM/64; it++) {
        int s0 = it * 64;

        if (it + 1 < S_DIM/64) issue(it + 1, (it + 1) & 1);

        // Prefetch ALL mask values for this tile NOW (global loads, independent
        // of smem buffers) so their latency overlaps qf reload + QK mma.
        float2 mb[2][8][2];   // [band][group=np*2+nb][{m0,m1}]
        #pragma unroll
        for (int band = 0; band < 2; band++)
            #pragma unroll
            for (int g = 0; g < 8; g++) {
                const float* mp = mrow[band] + s0 + g*8;
                mb[band][g][0] = *reinterpret_cast<const float2*>(mp);
                mb[band][g][1] = *reinterpret_cast<const float2*>(mp + 8*(size_t)S_DIM);
            }

        if (it + 1 < S_DIM/64) cp_wait1();
        else                   cp_wait0();
        __syncthreads();
        const __nv_bfloat16* Kb = Ks + (it & 1)*64*72;
        const __nv_bfloat16* Vb = Vs + (it & 1)*64*72;

        // reload Q fragments from resident smem tile (frees persistent regs)
        uint32_t qf[2][4][4];
        #pragma unroll
        for (int band = 0; band < 2; band++)
            #pragma unroll
            for (int kc = 0; kc < 4; kc++)
                ldmx4(qf[band][kc][0], qf[band][kc][1], qf[band][kc][2], qf[band][kc][3],
                      smem_u32(&Qs[(w*32 + band*16 + l7 + (g2 & 1)*8)*72 + kc*16 + (g2 >> 1)*8]));

        // S = Q @ K^T per npair (16 s-cols), +mask (prefetched), exp -> P fragments
        uint32_t pa[2][4][4];
        #pragma unroll
        for (int np = 0; np < 4; np++) {
            float c[2][2][4];
            #pragma unroll
            for (int band = 0; band < 2; band++)
                #pragma unroll
                for (int nb = 0; nb < 2; nb++)
                    #pragma unroll
                    for (int i = 0; i < 4; i++) c[band][nb][i] = 0.f;
            #pragma unroll
            for (int kc = 0; kc < 4; kc++) {
                uint32_t r0, r1, r2, r3;
                ldmx4(r0, r1, r2, r3,
                      smem_u32(&Kb[(np*16 + l7 + lb4*8)*72 + kc*16 + lb3*8]));
                #pragma unroll
                for (int band = 0; band < 2; band++) {
                    mma_bf16(c[band][0][0], c[band][0][1], c[band][0][2], c[band][0][3], qf[band][kc], r0, r1);
                    mma_bf16(c[band][1][0], c[band][1][1], c[band][1][2], c[band][1][3], qf[band][kc], r2, r3);
                }
            }
            #pragma unroll
            for (int band = 0; band < 2; band++) {
                #pragma unroll
                for (int nb = 0; nb < 2; nb++) {
                    float2 m0 = mb[band][np*2 + nb][0];
                    float2 m1 = mb[band][np*2 + nb][1];
                    float e0 = __expf(c[band][nb][0] + m0.x);
                    float e1 = __expf(c[band][nb][1] + m0.y);
                    float e2 = __expf(c[band][nb][2] + m1.x);
                    float e3 = __expf(c[band][nb][3] + m1.y);
                    ls[band][0] += e0 + e1;
                    ls[band][1] += e2 + e3;
                    pa[band][np][nb*2 + 0] = pkbf(e0, e1);
                    pa[band][np][nb*2 + 1] = pkbf(e2, e3);
                }
            }
        }

        // O += P @ V per dpair (16 d-cols)
        #pragma unroll
        for (int dp = 0; dp < 4; dp++) {
            #pragma unroll
            for (int kc = 0; kc < 4; kc++) {
                uint32_t r0, r1, r2, r3;
                ldmx4t(r0, r1, r2, r3,
                       smem_u32(&Vb[(kc*16 + l7 + lb3*8)*72 + dp*16 + lb4*8]));
                #pragma unroll
                for (int band = 0; band < 2; band++) {
                    mma_bf16(accO[band][dp*2+0][0], accO[band][dp*2+0][1], accO[band][dp*2+0][2], accO[band][dp*2+0][3], pa[band][kc], r0, r1);
                    mma_bf16(accO[band][dp*2+1][0], accO[band][dp*2+1][1], accO[band][dp*2+1][2], accO[band][dp*2+1][3], pa[band][kc], r2, r3);
                }
            }
        }
        __syncthreads();
    }

    // epilogue per band: reduce row sums across quads, normalize, store
    #pragma unroll
    for (int band = 0; band < 2; band++) {
        float slo = ls[band][0], shi = ls[band][1];
        slo += __shfl_xor_sync(0xffffffffu, slo, 1);
        slo += __shfl_xor_sync(0xffffffffu, slo, 2);
        shi += __shfl_xor_sync(0xffffffffu, shi, 1);
        shi += __shfl_xor_sync(0xffffffffu, shi, 2);
        float inv_lo = 1.f / slo, inv_hi = 1.f / shi;

        int row = t0 + w*32 + band*16 + (lane >> 2);
        float* o_lo = &g_ctx[((size_t)row*B_DIM + b)*NOUT + h*64 + (lane & 3)*2];
        float* o_hi = o_lo + (size_t)8*B_DIM*NOUT;
        #pragma unroll
        for (int d = 0; d < 8; d++) {
            float2 vlo = { accO[band][d][0]*inv_lo, accO[band][d][1]*inv_lo };
            float2 vhi = { accO[band][d][2]*inv_hi, accO[band][d][3]*inv_hi };
            *reinterpret_cast<float2*>(o_lo + d*8) = vlo;
            *reinterpret_cast<float2*>(o_hi + d*8) = vhi;
        }
    }
}

// ---------------------------------------------------------------------------
// Kernel 4: out = ctx @ Wo + bo  (fp32, unchanged)
// ---------------------------------------------------------------------------
__global__ void outproj_kernel(const float* __restrict__ Wo, const float* __restrict__ bo,
                               float* __restrict__ out)
{
    __shared__ float ctxT[64][68];
    int tid = threadIdx.x;
    int r0  = blockIdx.x * 64;
    int j   = tid & 63, rg = tid >> 6;
    float acc[16];
    #pragma unroll
    for (int i = 0; i < 16; i++) acc[i] = 0.f;

    #pragma unroll 1
    for (int kt = 0; kt < 8; kt++) {
        if (kt) __syncthreads();
        {
            int r = tid >> 2, q = tid & 3;
            #pragma unroll
            for (int i = 0; i < 4; i++) {
                int k = q*16 + i*4;
                float4 v4 = *reinterpret_cast<const float4*>(
                    &g_ctx[(size_t)(r0 + r)*NOUT + kt*64 + k]);
                ctxT[k+0][r] = v4.x;
                ctxT[k+1][r] = v4.y;
                ctxT[k+2][r] = v4.z;
                ctxT[k+3][r] = v4.w;
            }
        }
        __syncthreads();
        #pragma unroll 4
        for (int k = 0; k < 64; k++) {
            float wv = Wo[(size_t)(kt*64 + k)*64 + j];
            #pragma unroll
            for (int rr = 0; rr < 16; rr += 4) {
                float4 c4 = *reinterpret_cast<const float4*>(&ctxT[k][rg*16 + rr]);
                acc[rr+0] += wv * c4.x;
                acc[rr+1] += wv * c4.y;
                acc[rr+2] += wv * c4.z;
                acc[rr+3] += wv * c4.w;
            }
        }
    }
    float bj = bo[j];
    #pragma unroll
    for (int rr = 0; rr < 16; rr++)
        out[(size_t)(r0 + rg*16 + rr)*64 + j] = acc[rr] + bj;
}

// ---------------------------------------------------------------------------
extern "C" void kernel_launch(void* const* d_in, const int* in_sizes, int n_in,
                              void* d_out, int out_size)
{
    const float* query = (const float*)d_in[0];
    const float* key   = (const float*)d_in[1];
    const float* value = (const float*)d_in[2];
    const float* mask  = (const float*)d_in[3];
    const float* Wq1 = (const float*)d_in[4];  const float* bq1 = (const float*)d_in[5];
    const float* Wq2 = (const float*)d_in[6];  const float* bq2 = (const float*)d_in[7];
    const float* Wk1 = (const float*)d_in[8];  const float* bk1 = (const float*)d_in[9];
    const float* Wk2 = (const float*)d_in[10]; const float* bk2 = (const float*)d_in[11];
    const float* Wv1 = (const float*)d_in[12]; const float* bv1 = (const float*)d_in[13];
    const float* Wv2 = (const float*)d_in[14]; const float* bv2 = (const float*)d_in[15];
    const float* Wo  = (const float*)d_in[16];
    const float* bo  = (const float*)d_in[17];
    float* out = (float*)d_out;

    PrepSrc S;
    S.w[0] = Wq1; S.w[1] = Wk1; S.w[2] = Wv1;
    S.w[3] = Wq2; S.w[4] = Wk2; S.w[5] = Wv2;

    P1Args A1;
    A1.x[0] = query; A1.x[1] = key; A1.x[2] = value;
    A1.b1[0] = bq1;  A1.b1[1] = bk1; A1.b1[2] = bv1;

    P2Args A2;
    A2.b2[0] = bq2; A2.b2[1] = bk2; A2.b2[2] = bv2;
    A2.scale[0] = 0.125f; A2.scale[1] = 1.0f; A2.scale[2] = 1.0f;

    cudaFuncSetAttribute(p1_kernel, cudaFuncAttributeMaxDynamicSharedMemorySize, P1_SMEM);
    cudaFuncSetAttribute(p2_kernel, cudaFuncAttributeMaxDynamicSharedMemorySize, P2_SMEM);
    cudaFuncSetAttribute(attn_kernel, cudaFuncAttributeMaxDynamicSharedMemorySize, ATT_SMEM);

    prep_kernel<<<dim3(512, 6), 256>>>(S);
    p1_kernel<<<dim3(64, 3), 256, P1_SMEM>>>(A1);
    p2_kernel<<<dim3(64, 2, 3), 512, P2_SMEM>>>(A2);
    attn_kernel<<<dim3(16, 8, 4), 128, ATT_SMEM>>>(mask);
    outproj_kernel<<<128, 256>>>(Wo, bo, out);
}